// round 9
// baseline (speedup 1.0000x reference)
#include <cuda_runtime.h>
#include <cstdint>

#define BATCH   64
#define NV      68
#define MC      46
#define ZL      384
#define NE      368
#define NITERS  5
#define MAXDEG  16
#define LLRCLIP 20.0f

// ---------------- device scratch (no cudaMalloc allowed) ----------------
__device__ int8_t g_c2v[BATCH * NE * ZL];   // messages, CN-domain, value = 2*llr
__device__ float  g_tot[BATCH * NV * ZL];   // total belief, [B][N][Z]
__device__ float  g_acc[BATCH * NV * ZL];   // c2v sums (atomic), zero between iters
__device__ int2   g_meta[MC * MAXDEG];      // .x = (vn*ZL)<<9 | shift, .y = e*ZL
__device__ int    g_cn_deg[MC];

// ---------------- build check -> edge metadata --------------------------
__global__ void setup_kernel(const int* __restrict__ edge_cn,
                             const int* __restrict__ edge_vn,
                             const int* __restrict__ edge_shift) {
    int m = threadIdx.x;
    if (m < MC) {
        int d = 0;
        for (int e = 0; e < NE; e++) {
            if (edge_cn[e] == m && d < MAXDEG) {
                int2 md;
                md.x = ((edge_vn[e] * ZL) << 9) | (edge_shift[e] & 511);
                md.y = e * ZL;
                g_meta[m * MAXDEG + d] = md;
                d++;
            }
        }
        g_cn_deg[m] = d;
    }
}

// ---------------- CN update: min-sum + quantize + fused VN scatter ------
// grid (MC, BATCH), block ZL. Reads tot (xa when FIRST), writes c2v int8 and
// accumulates message llr into g_acc via fire-and-forget atomics (exact:
// all values are multiples of 0.5, order-independent in fp32).
template<bool FIRST>
__global__ __launch_bounds__(ZL, 4) void cn_kernel(
    const float* __restrict__ xa,
    const float* __restrict__ cn_weight,
    int it)
{
    const int m  = blockIdx.x;
    const int b  = blockIdx.y;
    const int zc = threadIdx.x;

    __shared__ int2 s_md[MAXDEG];
    int deg = g_cn_deg[m];
    if (deg > MAXDEG) deg = MAXDEG;
    if ((int)threadIdx.x < deg) s_md[threadIdx.x] = g_meta[m * MAXDEG + threadIdx.x];
    __syncthreads();

    const float w = cn_weight[it];
    const float* __restrict__ tot = (FIRST ? xa : g_tot) + (size_t)b * NV * ZL;
    float*       __restrict__ acc = g_acc + (size_t)b * NV * ZL;
    int8_t*      __restrict__ c2vb = g_c2v + (size_t)b * NE * ZL;

    if (deg == 8) {
        float vv[8]; int accoff[8], cidx[8];
        float m1 = 1e9f, m2 = 1e9f;
        int sgn = 0;
        #pragma unroll
        for (int k = 0; k < 8; k++) {
            int2 e = s_md[k];
            int z = zc - (e.x & 511); z += (z >> 31) & ZL;
            accoff[k] = (e.x >> 9) + z;
            cidx[k]   = e.y + zc;
            float c = FIRST ? 0.0f : 0.5f * (float)c2vb[cidx[k]];
            float t = __ldg(&tot[accoff[k]]);
            float v = fminf(fmaxf(t - c, -LLRCLIP), LLRCLIP);
            vv[k] = v;
            if (v < 0.0f) sgn ^= 1;
            float mag = fabsf(v);
            if (mag < m1)      { m2 = m1; m1 = mag; }
            else if (mag > m1) { m2 = fminf(m2, mag); }
        }
        // Only two possible quantized magnitudes per check; hoist the quantizer.
        // q(s*X) = s*q(X): rint (half-even) and the clamp are odd-symmetric.
        float r1 = fminf(fmaxf(rintf(2.0f * w * m1), -15.0f), 15.0f); // emin=m1 case
        float r2 = fminf(fmaxf(rintf(2.0f * w * m2), -15.0f), 15.0f); // emin=m2 case
        int   i1 = (int)r1,        i2 = (int)r2;
        float h1 = 0.5f * r1,      h2 = 0.5f * r2;
        #pragma unroll
        for (int k = 0; k < 8; k++) {
            float v   = vv[k];
            bool useb = (fabsf(v) == m1);     // entries tying min1 get min2
            bool s    = (v < 0.0f) ^ (sgn != 0);
            int   qi  = useb ? i2 : i1;
            float hv  = useb ? h2 : h1;
            c2vb[cidx[k]] = (int8_t)(s ? -qi : qi);
            atomicAdd(&acc[accoff[k]], s ? -hv : hv);
        }
    } else {
        // generic fallback (dataset uses deg==8)
        float m1 = 1e9f, m2 = 1e9f;
        int sgn = 0;
        for (int k = 0; k < deg; k++) {
            int2 e = s_md[k];
            int z = zc - (e.x & 511); z += (z >> 31) & ZL;
            float c = FIRST ? 0.0f : 0.5f * (float)c2vb[e.y + zc];
            float v = fminf(fmaxf(tot[(e.x >> 9) + z] - c, -LLRCLIP), LLRCLIP);
            if (v < 0.0f) sgn ^= 1;
            float mag = fabsf(v);
            if (mag < m1)      { m2 = m1; m1 = mag; }
            else if (mag > m1) { m2 = fminf(m2, mag); }
        }
        for (int k = 0; k < deg; k++) {
            int2 e = s_md[k];
            int z = zc - (e.x & 511); z += (z >> 31) & ZL;
            int ao = (e.x >> 9) + z;
            float c = FIRST ? 0.0f : 0.5f * (float)c2vb[e.y + zc];
            float v = fminf(fmaxf(tot[ao] - c, -LLRCLIP), LLRCLIP);
            float mag  = fabsf(v);
            float emin = (mag == m1) ? m2 : m1;
            bool flip  = (v < 0.0f) ^ (sgn != 0);
            float x    = (flip ? -w : w) * emin;
            float q2   = fminf(fmaxf(rintf(x + x), -15.0f), 15.0f);
            c2vb[e.y + zc] = (int8_t)q2;
            atomicAdd(&acc[ao], 0.5f * q2);
        }
    }
}

// ---------------- finalize: tot = xa + acc, acc = 0, out = tot^T --------
// grid (ZL/128, ceil(NV/32), BATCH), block 256.
// 128(z) x 32(n) tile: high-MLP loads, conflict-free padded transpose.
__global__ __launch_bounds__(256) void finalize_kernel(
    const float* __restrict__ xa,
    float*       __restrict__ out,     // slab for this iter: [B][ZL][NV]
    int write_tot)
{
    __shared__ float tile[32][129];    // [n][z], pad -> conflict-free transpose

    const int b    = blockIdx.z;
    const int z0   = blockIdx.x * 128;
    const int n0   = blockIdx.y * 32;
    const int nmax = (NV - n0 < 32) ? (NV - n0) : 32;
    const int tx   = threadIdx.x & 127;   // z within tile
    const int ty   = threadIdx.x >> 7;    // 0..1

    const size_t base = (size_t)b * NV * ZL;
    const float* __restrict__ xab  = xa    + base;
    float*       __restrict__ accb = g_acc + base;
    float*       __restrict__ totb = g_tot + base;

    #pragma unroll 4
    for (int nl = ty; nl < nmax; nl += 2) {
        int idx = (n0 + nl) * ZL + z0 + tx;
        float val = xab[idx] + accb[idx];
        accb[idx] = 0.0f;
        if (write_tot) totb[idx] = val;
        tile[nl][tx] = val;
    }
    __syncthreads();

    // out[b][z0+r][n0+n] = tile[n][r]; consecutive threads -> consecutive n
    float* __restrict__ ob = out + (size_t)b * ZL * NV;
    #pragma unroll 4
    for (int i = threadIdx.x; i < 128 * 32; i += 256) {
        int r = i >> 5;
        int n = i & 31;
        if (n < nmax) ob[(size_t)(z0 + r) * NV + n0 + n] = tile[n][r];
    }
}

// ---------------- launch -------------------------------------------------
extern "C" void kernel_launch(void* const* d_in, const int* in_sizes, int n_in,
                              void* d_out, int out_size)
{
    const float* xa   = (const float*)d_in[0];  // [B][N][Z]
    const float* cnw  = (const float*)d_in[1];  // [NITERS]
    const int*   evn  = (const int*)  d_in[2];  // [E]
    const int*   ecn  = (const int*)  d_in[3];  // [E]
    const int*   esh  = (const int*)  d_in[4];  // [E]
    float*       out  = (float*)d_out;          // [NITERS][B][Z][N]

    setup_kernel<<<1, 64>>>(ecn, evn, esh);

    const size_t slab = (size_t)BATCH * ZL * NV;
    dim3 cn_grid(MC, BATCH);
    dim3 fin_grid(ZL / 128, (NV + 31) / 32, BATCH);

    for (int it = 0; it < NITERS; it++) {
        if (it == 0) cn_kernel<true ><<<cn_grid, ZL>>>(xa, cnw, it);
        else         cn_kernel<false><<<cn_grid, ZL>>>(xa, cnw, it);
        // finalize always zeroes g_acc (keeps graph replays deterministic);
        // skips the g_tot write after the last iteration.
        finalize_kernel<<<fin_grid, 256>>>(xa, out + (size_t)it * slab,
                                           it == NITERS - 1 ? 0 : 1);
    }
}

// round 12
// speedup vs baseline: 1.3272x; 1.3272x over previous
#include <cuda_runtime.h>
#include <cstdint>

#define BATCH   64
#define NV      68
#define MC      46
#define ZL      384
#define NE      368
#define NITERS  5
#define MAXDEG  16
#define MAXVDEG 32
#define LLRCLIP 20.0f

// ---------------- device scratch (no cudaMalloc allowed) ----------------
__device__ int8_t g_c2v[BATCH * NE * ZL];     // messages, CN-domain, value = 2*llr
__device__ float  g_tot[BATCH * NV * ZL];     // total belief, [B][N][Z]
__device__ int2   g_meta[MC * MAXDEG];        // CN lists: .x=(vn*ZL)<<9|shift, .y=e*ZL
__device__ int    g_cn_deg[MC];
__device__ int2   g_vmeta[NV * MAXVDEG];      // VN lists: .x=e*ZL, .y=shift
__device__ int    g_vn_deg[NV];

// ---------------- build edge metadata (CN lists + VN lists) -------------
__global__ void setup_kernel(const int* __restrict__ edge_cn,
                             const int* __restrict__ edge_vn,
                             const int* __restrict__ edge_shift) {
    int t = threadIdx.x;
    if (t < MC) {
        int d = 0;
        for (int e = 0; e < NE; e++) {
            if (edge_cn[e] == t && d < MAXDEG) {
                int2 md;
                md.x = ((edge_vn[e] * ZL) << 9) | (edge_shift[e] & 511);
                md.y = e * ZL;
                g_meta[t * MAXDEG + d] = md;
                d++;
            }
        }
        g_cn_deg[t] = d;
    }
    if (t < NV) {
        int d = 0;
        for (int e = 0; e < NE; e++) {
            if (edge_vn[e] == t && d < MAXVDEG) {
                int2 md;
                md.x = e * ZL;
                md.y = edge_shift[e];
                g_vmeta[t * MAXVDEG + d] = md;
                d++;
            }
        }
        g_vn_deg[t] = d;
    }
}

// ---------------- CN update: min-sum + quantize (no atomics) ------------
// grid (MC, BATCH), block ZL. Reads tot (xa when FIRST), writes c2v int8.
template<bool FIRST>
__global__ __launch_bounds__(ZL) void cn_kernel(
    const float* __restrict__ xa,
    const float* __restrict__ cn_weight,
    int it)
{
    const int m  = blockIdx.x;
    const int b  = blockIdx.y;
    const int zc = threadIdx.x;

    __shared__ int2 s_md[MAXDEG];
    int deg = g_cn_deg[m];
    if (deg > MAXDEG) deg = MAXDEG;
    if ((int)threadIdx.x < deg) s_md[threadIdx.x] = g_meta[m * MAXDEG + threadIdx.x];
    __syncthreads();

    const float w = cn_weight[it];
    const float* __restrict__ tot = (FIRST ? xa : g_tot) + (size_t)b * NV * ZL;
    int8_t*      __restrict__ c2vb = g_c2v + (size_t)b * NE * ZL;

    if (deg == 8) {
        float vv[8]; int cidx[8];
        float m1 = 1e9f, m2 = 1e9f;
        int sgn = 0;
        #pragma unroll
        for (int k = 0; k < 8; k++) {
            int2 e = s_md[k];
            int z = zc - (e.x & 511); z += (z >> 31) & ZL;
            cidx[k] = e.y + zc;
            float c = FIRST ? 0.0f : 0.5f * (float)c2vb[cidx[k]];
            float t = __ldg(&tot[(e.x >> 9) + z]);
            float v = fminf(fmaxf(t - c, -LLRCLIP), LLRCLIP);
            vv[k] = v;
            if (v < 0.0f) sgn ^= 1;
            float mag = fabsf(v);
            if (mag < m1)      { m2 = m1; m1 = mag; }
            else if (mag > m1) { m2 = fminf(m2, mag); }
        }
        // Two possible quantized magnitudes per check; q is odd-symmetric.
        float r1 = fminf(fmaxf(rintf(2.0f * w * m1), -15.0f), 15.0f);
        float r2 = fminf(fmaxf(rintf(2.0f * w * m2), -15.0f), 15.0f);
        int i1 = (int)r1, i2 = (int)r2;
        #pragma unroll
        for (int k = 0; k < 8; k++) {
            float v   = vv[k];
            bool useb = (fabsf(v) == m1);       // ties on min1 get min2
            bool s    = (v < 0.0f) ^ (sgn != 0);
            int  qi   = useb ? i2 : i1;
            c2vb[cidx[k]] = (int8_t)(s ? -qi : qi);
        }
    } else {
        // generic fallback (dataset uses deg==8)
        float m1 = 1e9f, m2 = 1e9f;
        int sgn = 0;
        for (int k = 0; k < deg; k++) {
            int2 e = s_md[k];
            int z = zc - (e.x & 511); z += (z >> 31) & ZL;
            float c = FIRST ? 0.0f : 0.5f * (float)c2vb[e.y + zc];
            float v = fminf(fmaxf(tot[(e.x >> 9) + z] - c, -LLRCLIP), LLRCLIP);
            if (v < 0.0f) sgn ^= 1;
            float mag = fabsf(v);
            if (mag < m1)      { m2 = m1; m1 = mag; }
            else if (mag > m1) { m2 = fminf(m2, mag); }
        }
        for (int k = 0; k < deg; k++) {
            int2 e = s_md[k];
            int z = zc - (e.x & 511); z += (z >> 31) & ZL;
            float c = FIRST ? 0.0f : 0.5f * (float)c2vb[e.y + zc];
            float v = fminf(fmaxf(tot[(e.x >> 9) + z] - c, -LLRCLIP), LLRCLIP);
            float mag  = fabsf(v);
            float emin = (mag == m1) ? m2 : m1;
            bool flip  = (v < 0.0f) ^ (sgn != 0);
            float x    = (flip ? -w : w) * emin;
            float q2   = fminf(fmaxf(rintf(x + x), -15.0f), 15.0f);
            c2vb[e.y + zc] = (int8_t)q2;
        }
    }
}

// ---------------- VN update: gather c2v, tot = xa + sum, out = tot^T ----
// grid (ZL/64, BATCH), block 256: tz = z within 64-chunk, 4 n-quarters.
// Integer-exact gather (sum of int8 -> *0.5 -> +xa) matches segment_sum bitwise.
#define VZC  64
__global__ __launch_bounds__(256) void vn_kernel(
    const float* __restrict__ xa,
    float*       __restrict__ out,     // slab for this iter: [B][ZL][NV]
    int write_tot)
{
    __shared__ float tile[NV][VZC + 1];

    const int b  = blockIdx.y;
    const int z0 = blockIdx.x * VZC;
    const int tz = threadIdx.x & (VZC - 1);
    const int q  = threadIdx.x >> 6;          // n-quarter 0..3
    const int z  = z0 + tz;

    const size_t base = (size_t)b * NV * ZL;
    const float* __restrict__ xab  = xa    + base;
    float*       __restrict__ totb = g_tot + base;
    const int8_t* __restrict__ c2vb = g_c2v + (size_t)b * NE * ZL;

    const int nbeg = q * 17;
    const int nend = nbeg + 17;
    for (int n = nbeg; n < nend; n++) {
        int d = g_vn_deg[n];
        const int2* __restrict__ vm = &g_vmeta[n * MAXVDEG];
        float s = 0.0f;
        for (int j = 0; j < d; j++) {
            int2 md = __ldg(&vm[j]);
            int zc = z + md.y; if (zc >= ZL) zc -= ZL;
            s += (float)c2vb[md.x + zc];       // exact integer accumulation
        }
        float val = 0.5f * s + xab[n * ZL + z];
        if (write_tot) totb[n * ZL + z] = val;
        tile[n][tz] = val;
    }
    __syncthreads();

    // out[b][z0+zl][n] = tile[n][zl]; consecutive threads -> consecutive n
    float* __restrict__ ob = out + ((size_t)b * ZL + z0) * NV;
    for (int i = threadIdx.x; i < VZC * NV; i += 256) {
        int zl = i / NV, n = i - zl * NV;
        ob[(size_t)zl * NV + n] = tile[n][zl];
    }
}

// ---------------- launch -------------------------------------------------
extern "C" void kernel_launch(void* const* d_in, const int* in_sizes, int n_in,
                              void* d_out, int out_size)
{
    const float* xa   = (const float*)d_in[0];  // [B][N][Z]
    const float* cnw  = (const float*)d_in[1];  // [NITERS]
    const int*   evn  = (const int*)  d_in[2];  // [E]
    const int*   ecn  = (const int*)  d_in[3];  // [E]
    const int*   esh  = (const int*)  d_in[4];  // [E]
    float*       out  = (float*)d_out;          // [NITERS][B][Z][N]

    setup_kernel<<<1, 128>>>(ecn, evn, esh);

    const size_t slab = (size_t)BATCH * ZL * NV;
    dim3 cn_grid(MC, BATCH);
    dim3 vn_grid(ZL / VZC, BATCH);

    for (int it = 0; it < NITERS; it++) {
        if (it == 0) cn_kernel<true ><<<cn_grid, ZL>>>(xa, cnw, it);
        else         cn_kernel<false><<<cn_grid, ZL>>>(xa, cnw, it);
        vn_kernel<<<vn_grid, 256>>>(xa, out + (size_t)it * slab,
                                    it == NITERS - 1 ? 0 : 1);
    }
}

// round 13
// speedup vs baseline: 1.8157x; 1.3681x over previous
#include <cuda_runtime.h>
#include <cstdint>

#define BATCH   64
#define NV      68
#define MC      46
#define ZL      384
#define NE      368
#define NITERS  5
#define MAXDEG  16
#define MAXVDEG 32
#define LLRCLIP 20.0f

// ---------------- device scratch (no cudaMalloc allowed) ----------------
__device__ __align__(16) int8_t g_c2v[BATCH * NE * ZL]; // messages, CN-domain, 2*llr
__device__ float  g_tot[BATCH * NV * ZL];               // total belief, [B][N][Z]
__device__ int2   g_meta[MC * MAXDEG];                  // .x=(vn*ZL)<<9|shift, .y=e*ZL
__device__ int    g_cn_deg[MC];
__device__ int2   g_vmeta[NV * MAXVDEG];                // .x=e*ZL, .y=shift
__device__ int    g_vn_deg[NV];

// ---------------- build edge metadata (parallel; list order irrelevant:
// min-sum mins, sign-xor and integer sums are order-independent) ---------
__global__ void setup_kernel(const int* __restrict__ edge_cn,
                             const int* __restrict__ edge_vn,
                             const int* __restrict__ edge_shift) {
    __shared__ int ccnt[MC], vcnt[NV];
    int t = threadIdx.x;
    if (t < MC) ccnt[t] = 0;
    if (t < NV) vcnt[t] = 0;
    __syncthreads();
    if (t < NE) {
        int m = edge_cn[t], n = edge_vn[t], sh = edge_shift[t];
        int slot = atomicAdd(&ccnt[m], 1);
        if (slot < MAXDEG) {
            int2 md; md.x = ((n * ZL) << 9) | (sh & 511); md.y = t * ZL;
            g_meta[m * MAXDEG + slot] = md;
        }
        int vslot = atomicAdd(&vcnt[n], 1);
        if (vslot < MAXVDEG) {
            int2 vm; vm.x = t * ZL; vm.y = sh;
            g_vmeta[n * MAXVDEG + vslot] = vm;
        }
    }
    __syncthreads();
    if (t < MC) g_cn_deg[t] = min(ccnt[t], MAXDEG);
    if (t < NV) g_vn_deg[t] = min(vcnt[t], MAXVDEG);
}

// ---------------- CN update: SMEM-staged tot, min-sum + quantize --------
// grid (MC, BATCH), block ZL. Stages this check's 8 tot rows in SMEM so the
// shifted gathers are conflict-free LDS instead of scalar L2 loads.
template<bool FIRST>
__global__ __launch_bounds__(ZL) void cn_kernel(
    const float* __restrict__ xa,
    const float* __restrict__ cn_weight,
    int it)
{
    const int m  = blockIdx.x;
    const int b  = blockIdx.y;
    const int zc = threadIdx.x;

    __shared__ float s_tot[8 * ZL];   // 12 KB (deg==8 fast path)
    __shared__ int2  s_md[MAXDEG];
    __shared__ int   s_degs;

    if (threadIdx.x == 0) s_degs = g_cn_deg[m];
    if (threadIdx.x < MAXDEG) s_md[threadIdx.x] = g_meta[m * MAXDEG + threadIdx.x];
    __syncthreads();

    const int deg = s_degs;
    const float w = cn_weight[it];
    const float* __restrict__ tot = (FIRST ? xa : g_tot) + (size_t)b * NV * ZL;
    int8_t*      __restrict__ c2vb = g_c2v + (size_t)b * NE * ZL;

    if (deg == 8) {
        // cooperative load: 8 rows x 384 floats = 768 float4, 2 per thread
        #pragma unroll
        for (int f = 0; f < 2; f++) {
            int fi  = threadIdx.x + f * ZL;     // float4 index 0..767
            int row = fi / 96, off = fi - row * 96;
            int rb  = s_md[row].x >> 9;
            *(float4*)&s_tot[row * ZL + off * 4] =
                *(const float4*)(tot + rb + off * 4);
        }
        __syncthreads();

        float vv[8]; int cidx[8];
        float m1 = 1e9f, m2 = 1e9f;
        int sgn = 0;
        #pragma unroll
        for (int k = 0; k < 8; k++) {
            int2 e = s_md[k];
            int z = zc - (e.x & 511); z += (z >> 31) & ZL;
            cidx[k] = e.y + zc;
            float c = FIRST ? 0.0f : 0.5f * (float)c2vb[cidx[k]];
            float t = s_tot[k * ZL + z];         // conflict-free LDS
            float v = fminf(fmaxf(t - c, -LLRCLIP), LLRCLIP);
            vv[k] = v;
            if (v < 0.0f) sgn ^= 1;
            float mag = fabsf(v);
            if (mag < m1)      { m2 = m1; m1 = mag; }
            else if (mag > m1) { m2 = fminf(m2, mag); }
        }
        // two possible quantized magnitudes per check; q odd-symmetric
        float r1 = fminf(fmaxf(rintf(2.0f * w * m1), -15.0f), 15.0f);
        float r2 = fminf(fmaxf(rintf(2.0f * w * m2), -15.0f), 15.0f);
        int i1 = (int)r1, i2 = (int)r2;
        #pragma unroll
        for (int k = 0; k < 8; k++) {
            bool useb = (fabsf(vv[k]) == m1);    // ties on min1 get min2
            bool s    = (vv[k] < 0.0f) ^ (sgn != 0);
            int  qi   = useb ? i2 : i1;
            c2vb[cidx[k]] = (int8_t)(s ? -qi : qi);
        }
    } else {
        // generic fallback: direct global gathers (dataset uses deg==8)
        float m1 = 1e9f, m2 = 1e9f;
        int sgn = 0;
        for (int k = 0; k < deg; k++) {
            int2 e = s_md[k];
            int z = zc - (e.x & 511); z += (z >> 31) & ZL;
            float c = FIRST ? 0.0f : 0.5f * (float)c2vb[e.y + zc];
            float v = fminf(fmaxf(tot[(e.x >> 9) + z] - c, -LLRCLIP), LLRCLIP);
            if (v < 0.0f) sgn ^= 1;
            float mag = fabsf(v);
            if (mag < m1)      { m2 = m1; m1 = mag; }
            else if (mag > m1) { m2 = fminf(m2, mag); }
        }
        for (int k = 0; k < deg; k++) {
            int2 e = s_md[k];
            int z = zc - (e.x & 511); z += (z >> 31) & ZL;
            float c = FIRST ? 0.0f : 0.5f * (float)c2vb[e.y + zc];
            float v = fminf(fmaxf(tot[(e.x >> 9) + z] - c, -LLRCLIP), LLRCLIP);
            float mag  = fabsf(v);
            float emin = (mag == m1) ? m2 : m1;
            bool flip  = (v < 0.0f) ^ (sgn != 0);
            float x    = (flip ? -w : w) * emin;
            float q2   = fminf(fmaxf(rintf(x + x), -15.0f), 15.0f);
            c2vb[e.y + zc] = (int8_t)q2;
        }
    }
}

// ---------------- VN update: 4z-vectorized gather via funnel shift ------
// grid (ZL/32, BATCH), block 256 = 8 z-groups(4z) x 32 n-groups.
// Integer-exact accumulation -> *0.5 -> +xa matches segment_sum bitwise.
#define VZC 32
__global__ __launch_bounds__(256) void vn_kernel(
    const float* __restrict__ xa,
    float*       __restrict__ out,     // slab for this iter: [B][ZL][NV]
    int write_tot)
{
    __shared__ float tile[NV][VZC + 1];

    const int b  = blockIdx.y;
    const int z0 = blockIdx.x * VZC;
    const int zg = threadIdx.x & 7;        // 8 groups of 4 z
    const int ng = threadIdx.x >> 3;       // 0..31
    const int zl = zg * 4;
    const int z  = z0 + zl;

    const size_t base = (size_t)b * NV * ZL;
    const float* __restrict__ xab  = xa    + base;
    float*       __restrict__ totb = g_tot + base;
    const int8_t* __restrict__ c2vb = g_c2v + (size_t)b * NE * ZL;

    for (int n = ng; n < NV; n += 32) {
        int d = g_vn_deg[n];
        const int2* __restrict__ vm = &g_vmeta[n * MAXVDEG];
        int s0 = 0, s1 = 0, s2 = 0, s3 = 0;
        for (int j = 0; j < d; j++) {
            int2 md = __ldg(&vm[j]);
            int zc0 = z + md.y; if (zc0 >= ZL) zc0 -= ZL;
            int a0 = zc0 & ~3;
            int a1 = a0 + 4; if (a1 >= ZL) a1 = 0;
            unsigned w0 = *(const unsigned*)(c2vb + md.x + a0);
            unsigned w1 = *(const unsigned*)(c2vb + md.x + a1);
            unsigned v  = __funnelshift_r(w0, w1, (zc0 & 3) * 8);
            s0 += (int)(v << 24) >> 24;
            s1 += (int)(v << 16) >> 24;
            s2 += (int)(v <<  8) >> 24;
            s3 += (int)v >> 24;
        }
        float4 xv = *(const float4*)(xab + n * ZL + z);
        float4 r;
        r.x = 0.5f * (float)s0 + xv.x;
        r.y = 0.5f * (float)s1 + xv.y;
        r.z = 0.5f * (float)s2 + xv.z;
        r.w = 0.5f * (float)s3 + xv.w;
        if (write_tot) *(float4*)(totb + n * ZL + z) = r;
        tile[n][zl + 0] = r.x;
        tile[n][zl + 1] = r.y;
        tile[n][zl + 2] = r.z;
        tile[n][zl + 3] = r.w;
    }
    __syncthreads();

    // out[b][z0+zz][n] = tile[n][zz]; consecutive threads -> consecutive n
    float* __restrict__ ob = out + ((size_t)b * ZL + z0) * NV;
    for (int i = threadIdx.x; i < VZC * NV; i += 256) {
        int zz = i / NV, n = i - zz * NV;
        ob[(size_t)zz * NV + n] = tile[n][zz];
    }
}

// ---------------- launch -------------------------------------------------
extern "C" void kernel_launch(void* const* d_in, const int* in_sizes, int n_in,
                              void* d_out, int out_size)
{
    const float* xa   = (const float*)d_in[0];  // [B][N][Z]
    const float* cnw  = (const float*)d_in[1];  // [NITERS]
    const int*   evn  = (const int*)  d_in[2];  // [E]
    const int*   ecn  = (const int*)  d_in[3];  // [E]
    const int*   esh  = (const int*)  d_in[4];  // [E]
    float*       out  = (float*)d_out;          // [NITERS][B][Z][N]

    setup_kernel<<<1, 384>>>(ecn, evn, esh);

    const size_t slab = (size_t)BATCH * ZL * NV;
    dim3 cn_grid(MC, BATCH);
    dim3 vn_grid(ZL / VZC, BATCH);

    for (int it = 0; it < NITERS; it++) {
        if (it == 0) cn_kernel<true ><<<cn_grid, ZL>>>(xa, cnw, it);
        else         cn_kernel<false><<<cn_grid, ZL>>>(xa, cnw, it);
        vn_kernel<<<vn_grid, 256>>>(xa, out + (size_t)it * slab,
                                    it == NITERS - 1 ? 0 : 1);
    }
}